// round 11
// baseline (speedup 1.0000x reference)
#include <cuda_runtime.h>
#include <math.h>
#include <stdint.h>

#define BQ 8
#define HH 56
#define WW 56
#define LL 3136          // HH*WW
#define BL 25088         // BQ*LL
#define DMODEL 384
#define DINNER 768
#define NH 12
#define HD 64
#define DST 64
#define CONVD 896        // DINNER + 2*DSTATE
#define DPROJ 1676       // 2*DINNER + 2*DSTATE + NH

// ---------------- scratch (device globals: allocation-free contract) ----------------
__device__ float g_z[(size_t)BL * DINNER];      // z branch
__device__ float g_xBC[(size_t)BL * CONVD];     // pre-conv xBC
__device__ float g_dt[(size_t)BL * NH];         // softplus(dt + bias)
__device__ float g_xBCa[(size_t)BL * CONVD];    // post conv+silu  (xs | B | C)
__device__ float g_y[(size_t)BL * DINNER];      // y (ch output)
__device__ float g_dxp[(size_t)BL * DINNER];    // pooled dx
__device__ float g_hstate[BQ * NH * DST * HD];  // per (b,h) 64x64 state
__device__ float g_gn[(size_t)BL * DINNER];     // post-LN (tf32-rounded, k-permuted)
__device__ float g_xcvt[(size_t)BL * DMODEL];   // tf32-rounded, k-permuted x
__device__ float g_wincvt[(size_t)DPROJ * DMODEL];   // tf32, k-permuted in_proj_w
__device__ float g_woutcvt[(size_t)DMODEL * DINNER]; // tf32, k-permuted out_proj_w
__device__ float g_negA[DINNER];                // -exp(A_log)
__device__ float g_cwT[9 * CONVD];              // conv weights transposed [tap][c]

__device__ __forceinline__ uint32_t f2tf32(float f) {
    uint32_t u;
    asm("cvt.rna.tf32.f32 %0, %1;" : "=r"(u) : "f"(f));
    return u;
}
__device__ __forceinline__ uint32_t smem_u32(const void* p) {
    uint32_t a;
    asm("{ .reg .u64 t; cvta.to.shared.u64 t, %1; cvt.u32.u64 %0, t; }"
        : "=r"(a) : "l"(p));
    return a;
}
__device__ __forceinline__ void mma_tf32(float c[4], float a0, float a1,
                                         float a2, float a3,
                                         float b0, float b1) {
    asm volatile(
        "mma.sync.aligned.m16n8k8.row.col.f32.tf32.tf32.f32 "
        "{%0,%1,%2,%3}, {%4,%5,%6,%7}, {%8,%9}, {%0,%1,%2,%3};"
        : "+f"(c[0]), "+f"(c[1]), "+f"(c[2]), "+f"(c[3])
        : "r"(__float_as_uint(a0)), "r"(__float_as_uint(a1)),
          "r"(__float_as_uint(a2)), "r"(__float_as_uint(a3)),
          "r"(__float_as_uint(b0)), "r"(__float_as_uint(b1)));
}
__device__ __forceinline__ void cpa16(uint32_t dst, const void* src, int srcbytes) {
    asm volatile("cp.async.cg.shared.global [%0], [%1], 16, %2;"
                 :: "r"(dst), "l"(src), "r"(srcbytes) : "memory");
}
__device__ __forceinline__ void cpa_commit() {
    asm volatile("cp.async.commit_group;" ::: "memory");
}
__device__ __forceinline__ void cpa_wait2() {
    asm volatile("cp.async.wait_group 2;" ::: "memory");
}

// ------- tf32-round + k-permute: within each 16-float group, pos = ((k&3)<<2)|(k>>2) -------
__global__ void __launch_bounds__(256) cvt_perm_kernel(
    const float* __restrict__ src, float* __restrict__ dst, int ngroups)
{
    const int g = blockIdx.x * 256 + threadIdx.x;
    if (g >= ngroups) return;
    const float4* s = (const float4*)src + (size_t)g * 4;
    float4 v0 = s[0], v1 = s[1], v2 = s[2], v3 = s[3];
    uint4 o0, o1, o2, o3;
    o0.x = f2tf32(v0.x); o0.y = f2tf32(v1.x); o0.z = f2tf32(v2.x); o0.w = f2tf32(v3.x);
    o1.x = f2tf32(v0.y); o1.y = f2tf32(v1.y); o1.z = f2tf32(v2.y); o1.w = f2tf32(v3.y);
    o2.x = f2tf32(v0.z); o2.y = f2tf32(v1.z); o2.z = f2tf32(v2.z); o2.w = f2tf32(v3.z);
    o3.x = f2tf32(v0.w); o3.y = f2tf32(v1.w); o3.z = f2tf32(v2.w); o3.w = f2tf32(v3.w);
    uint4* d = (uint4*)dst + (size_t)g * 4;
    d[0] = o0; d[1] = o1; d[2] = o2; d[3] = o3;
}

// ---------------- prep: -exp(A_log) + conv-weight transpose [c][9] -> [tap][c] ----------------
__global__ void prep_kernel(const float* __restrict__ A_log, const float* __restrict__ cw)
{
    const int i = threadIdx.x + blockIdx.x * 256;
    if (i < DINNER) g_negA[i] = -expf(A_log[i]);
    if (i < 9 * CONVD) {
        const int c = i / 9, t = i - c * 9;
        g_cwT[t * CONVD + c] = cw[i];
    }
}

// ============ tf32 mma.sync GEMM, 256x128 CTA tile, k-permuted LDS.128 fragments ============
// 512 thr = 16 warps (4m x 4n), warp tile 64x32 (same per-warp code/regs as R8/R10).
// LDGSTS per FLOP cut 25% vs 128x128 (fill-issue-bound fix).
#define STAGEB_A (256 * 16 * 4)       // 16384 B per stage
#define STAGEB_B (128 * 16 * 4)       // 8192 B per stage
#define GSTAGES 4
#define GEMM_DSMEM (GSTAGES * (STAGEB_A + STAGEB_B) + 128)

template <int KDIM, int MODE>
__global__ void __launch_bounds__(512) gemm_mma(
    float* __restrict__ out, const float* __restrict__ dt_bias, int N)
{
    extern __shared__ char raw_smem[];
    const uint32_t raw_u = smem_u32(raw_smem);
    const uint32_t dsm_u = (raw_u + 127u) & ~127u;
    char* dsm = raw_smem + (dsm_u - raw_u);

    const int tid = threadIdx.x;
    const int lane = tid & 31;
    const int warp = tid >> 5;          // 0..15
    const int bm = blockIdx.y * 256;
    const int bn = blockIdx.x * 128;
    const int wm = (warp >> 2) * 64;    // 0/64/128/192
    const int wn = (warp & 3) * 32;     // 0/32/64/96
    const int mrow = lane >> 2;
    const int kc = (lane & 3) * 4;

    const float* Ap = (MODE == 0) ? g_xcvt : g_gn;
    const float* Bp = (MODE == 0) ? g_wincvt : g_woutcvt;

    float acc[4][4][4];
#pragma unroll
    for (int i = 0; i < 4; i++)
#pragma unroll
        for (int j = 0; j < 4; j++)
#pragma unroll
            for (int r = 0; r < 4; r++) acc[i][j][r] = 0.f;

    // loader: A 1024 chunks (2/thread), B 512 chunks (1/thread) per stage
    auto issue_stage = [&](int kt, int s) {
        const int k0 = kt * 16;
        const uint32_t abase = dsm_u + s * STAGEB_A;
        const uint32_t bbase = dsm_u + GSTAGES * STAGEB_A + s * STAGEB_B;
#pragma unroll
        for (int i = 0; i < 2; i++) {
            const int c = tid + i * 512;
            const int row = c >> 2;             // 0..255
            const int q = c & 3;
            cpa16(abase + (uint32_t)(row * 64 + q * 16),
                  Ap + (size_t)(bm + row) * KDIM + k0 + q * 4, 16);
        }
        {
            const int row = tid >> 2;           // 0..127
            const int q = tid & 3;
            const int nb = bn + row;
            const int okB = (MODE == 1 || nb < N) ? 16 : 0;
            const int nbs = (MODE == 1 || nb < N) ? nb : (N - 1);
            cpa16(bbase + (uint32_t)(row * 64 + q * 16),
                  Bp + (size_t)nbs * KDIM + k0 + q * 4, okB);
        }
    };

    constexpr int KT = KDIM / 16;
#pragma unroll
    for (int p = 0; p < GSTAGES - 1; p++) {
        issue_stage(p, p);
        cpa_commit();
    }

#pragma unroll 1
    for (int kt = 0; kt < KT; kt++) {
        const int s = kt & (GSTAGES - 1);
        cpa_wait2();
        __syncthreads();

        const float* Asb = (const float*)(dsm + s * STAGEB_A);
        const float* Bsb = (const float*)(dsm + GSTAGES * STAGEB_A + s * STAGEB_B);

        float4 bf[4];
#pragma unroll
        for (int j = 0; j < 4; j++) {
            const int n = wn + j * 8 + mrow;
            bf[j] = *(const float4*)&Bsb[n * 16 + kc];
        }
#pragma unroll
        for (int i = 0; i < 4; i++) {
            const int m = wm + i * 16 + mrow;
            float4 aL = *(const float4*)&Asb[m * 16 + kc];
            float4 aH = *(const float4*)&Asb[(m + 8) * 16 + kc];
#pragma unroll
            for (int j = 0; j < 4; j++) {
                mma_tf32(acc[i][j], aL.x, aH.x, aL.y, aH.y, bf[j].x, bf[j].y);
                mma_tf32(acc[i][j], aL.z, aH.z, aL.w, aH.w, bf[j].z, bf[j].w);
            }
        }

        const int nk = kt + GSTAGES - 1;
        if (nk < KT) issue_stage(nk, nk & (GSTAGES - 1));
        cpa_commit();
    }

    // ---- epilogue: fragment (r, r+1) pairs adjacent in n -> STG.64 ----
#pragma unroll
    for (int i = 0; i < 4; i++) {
        const int m0 = bm + wm + i * 16 + mrow;     // rows m0 and m0+8
#pragma unroll
        for (int j = 0; j < 4; j++) {
            const int n = bn + wn + j * 8 + (lane & 3) * 2;
            const float2 p0 = make_float2(acc[i][j][0], acc[i][j][1]);
            const float2 p1 = make_float2(acc[i][j][2], acc[i][j][3]);
            if (MODE == 1) {
                *(float2*)(out + (size_t)m0 * DMODEL + n) = p0;
                *(float2*)(out + (size_t)(m0 + 8) * DMODEL + n) = p1;
            } else {
                if (n < DINNER) {
                    *(float2*)(g_z + (size_t)m0 * DINNER + n) = p0;
                    *(float2*)(g_z + (size_t)(m0 + 8) * DINNER + n) = p1;
                } else if (n < DINNER + CONVD) {
                    const int nn = n - DINNER;
                    *(float2*)(g_xBC + (size_t)m0 * CONVD + nn) = p0;
                    *(float2*)(g_xBC + (size_t)(m0 + 8) * CONVD + nn) = p1;
                } else {
                    const float vv[4] = {p0.x, p0.y, p1.x, p1.y};
#pragma unroll
                    for (int r = 0; r < 4; r++) {
                        const int ne = n + (r & 1);
                        if (ne < DPROJ) {
                            const int m = m0 + (r >> 1) * 8;
                            const int h = ne - (DINNER + CONVD);
                            const float t = vv[r] + dt_bias[h];
                            g_dt[(size_t)m * NH + h] =
                                (t > 20.f) ? t : log1pf(expf(t));
                        }
                    }
                }
            }
        }
    }
}

// ------- depthwise 3x3 conv + bias + silu, float4 channels (224 thr/block) -------
__global__ void __launch_bounds__(224) conv_kernel(const float* __restrict__ cb)
{
    const int c = threadIdx.x * 4;                  // 0..892
    const int bl = blockIdx.x;
    const int b = bl / LL;
    const int l = bl - b * LL;
    const int y = l / WW;
    const int x = l - y * WW;

    float4 acc = *(const float4*)(cb + c);
#pragma unroll
    for (int dy = -1; dy <= 1; dy++) {
        const int yy = y + dy;
        if (yy < 0 || yy >= HH) continue;
#pragma unroll
        for (int dx = -1; dx <= 1; dx++) {
            const int xx = x + dx;
            if (xx < 0 || xx >= WW) continue;
            const float4 v = *(const float4*)(g_xBC +
                ((size_t)(b * LL + yy * WW + xx)) * CONVD + c);
            const float4 w = *(const float4*)(g_cwT + ((dy + 1) * 3 + (dx + 1)) * CONVD + c);
            acc.x = fmaf(v.x, w.x, acc.x);
            acc.y = fmaf(v.y, w.y, acc.y);
            acc.z = fmaf(v.z, w.z, acc.z);
            acc.w = fmaf(v.w, w.w, acc.w);
        }
    }
    float4 o;
    o.x = acc.x / (1.f + expf(-acc.x));
    o.y = acc.y / (1.f + expf(-acc.y));
    o.z = acc.z / (1.f + expf(-acc.z));
    o.w = acc.w / (1.f + expf(-acc.w));
    *(float4*)(g_xBCa + (size_t)bl * CONVD + c) = o;
}

// ---- fused dx + 3x3 count-normalized pool, float4 channels (192 thr/block) ----
__global__ void __launch_bounds__(192) dxpool_kernel()
{
    const int c = threadIdx.x * 4;                  // 0..764
    const int bl = blockIdx.x;
    const int b = bl / LL;
    const int l = bl - b * LL;
    const int y = l / WW;
    const int x = l - y * WW;
    const int h = c >> 6;

    const int y0 = max(y - 1, 0), y1 = min(y + 1, HH - 1);
    const int x0 = max(x - 1, 0), x1 = min(x + 1, WW - 1);
    float4 s = make_float4(0.f, 0.f, 0.f, 0.f);
    for (int yy = y0; yy <= y1; yy++)
        for (int xx = x0; xx <= x1; xx++) {
            const size_t nb = (size_t)(b * LL + yy * WW + xx);
            const float4 v = *(const float4*)(g_xBCa + nb * CONVD + c);
            const float dtv = g_dt[nb * NH + h];
            s.x = fmaf(v.x, dtv, s.x);
            s.y = fmaf(v.y, dtv, s.y);
            s.z = fmaf(v.z, dtv, s.z);
            s.w = fmaf(v.w, dtv, s.w);
        }
    const float inv = 1.f / (float)((y1 - y0 + 1) * (x1 - x0 + 1));
    const float4 na = *(const float4*)(g_negA + c);
    float4 o;
    o.x = s.x * na.x * inv;
    o.y = s.y * na.y * inv;
    o.z = s.z * na.z * inv;
    o.w = s.w * na.w * inv;
    *(float4*)(g_dxp + (size_t)bl * DINNER + c) = o;
}

// ---------------- zero h_state ----------------
__global__ void zero_hstate()
{
    const int i = blockIdx.x * 256 + threadIdx.x;
    ((float4*)g_hstate)[i] = make_float4(0.f, 0.f, 0.f, 0.f);
}

// ---------------- h_state[b,h,s,d] += sum_l B[b,l,s] * dxp[b,l,h,d] (split-K over L) ----
__global__ void __launch_bounds__(256) hstate_kernel()
{
    const int b = blockIdx.z;
    const int h = blockIdx.y;
    const int l0 = blockIdx.x * 448;

    __shared__ __align__(16) float Bs[16][64];
    __shared__ __align__(16) float Ds[16][64];

    const int tid = threadIdx.x;
    const int ty = tid >> 4, tx = tid & 15;
    const int lr = tid >> 4;
    const int f4 = (tid & 15) * 4;

    float acc[4][4];
#pragma unroll
    for (int i = 0; i < 4; i++)
#pragma unroll
        for (int j = 0; j < 4; j++) acc[i][j] = 0.f;

    for (int lt = 0; lt < 448; lt += 16) {
        const int l = l0 + lt + lr;
        const size_t rb = (size_t)(b * LL + l);
        *(float4*)&Bs[lr][f4] = *(const float4*)(g_xBCa + rb * CONVD + DINNER + f4);
        *(float4*)&Ds[lr][f4] = *(const float4*)(g_dxp + rb * DINNER + h * HD + f4);
        __syncthreads();
#pragma unroll
        for (int kk = 0; kk < 16; kk++) {
            float4 a = *(const float4*)&Bs[kk][ty * 4];
            float4 d = *(const float4*)&Ds[kk][tx * 4];
            float av[4] = {a.x, a.y, a.z, a.w};
            float dv[4] = {d.x, d.y, d.z, d.w};
#pragma unroll
            for (int i = 0; i < 4; i++)
#pragma unroll
                for (int j = 0; j < 4; j++)
                    acc[i][j] = fmaf(av[i], dv[j], acc[i][j]);
        }
        __syncthreads();
    }

    float* hp = g_hstate + (size_t)(b * NH + h) * DST * HD;
#pragma unroll
    for (int i = 0; i < 4; i++)
#pragma unroll
        for (int j = 0; j < 4; j++)
            atomicAdd(&hp[(ty * 4 + i) * HD + tx * 4 + j], acc[i][j]);
}

// ---------------- y[b,l,h,d] = sum_s C[b,l,s]*hstate[b,h,s,d] + xs * D[h] ----------------
__global__ void __launch_bounds__(256) ch_kernel(const float* __restrict__ Dp)
{
    const int b = blockIdx.z;
    const int h = blockIdx.y;
    const int l0 = blockIdx.x * 64;

    __shared__ __align__(16) float Hs[64][64];   // [s][d]
    __shared__ __align__(16) float Cs[64][68];   // [s][l] (transposed)

    const int tid = threadIdx.x;
    const int ty = tid >> 4, tx = tid & 15;

    {
        const float4* hsrc = (const float4*)(g_hstate + (size_t)(b * NH + h) * DST * HD);
        float4* hdst = (float4*)Hs;
#pragma unroll
        for (int i = 0; i < 4; i++) hdst[tid + i * 256] = hsrc[tid + i * 256];
    }
    {
        const int lr = tid >> 2;
        const int base = (tid & 3) * 4;
        const float* crow = g_xBCa + (size_t)(b * LL + l0 + lr) * CONVD + DINNER + DST;
#pragma unroll
        for (int it = 0; it < 4; it++) {
            const int sq = base + it * 16;
            float4 v = *(const float4*)(crow + sq);
            Cs[sq + 0][lr] = v.x; Cs[sq + 1][lr] = v.y;
            Cs[sq + 2][lr] = v.z; Cs[sq + 3][lr] = v.w;
        }
    }
    __syncthreads();

    float acc[4][4];
#pragma unroll
    for (int i = 0; i < 4; i++)
#pragma unroll
        for (int j = 0; j < 4; j++) acc[i][j] = 0.f;

#pragma unroll 16
    for (int s = 0; s < 64; s++) {
        float4 a = *(const float4*)&Cs[s][ty * 4];
        float4 hv = *(const float4*)&Hs[s][tx * 4];
        float av[4] = {a.x, a.y, a.z, a.w};
        float hvv[4] = {hv.x, hv.y, hv.z, hv.w};
#pragma unroll
        for (int i = 0; i < 4; i++)
#pragma unroll
            for (int j = 0; j < 4; j++)
                acc[i][j] = fmaf(av[i], hvv[j], acc[i][j]);
    }

    const float dcoef = Dp[h];
#pragma unroll
    for (int i = 0; i < 4; i++) {
        const int l = l0 + ty * 4 + i;
        const size_t r = (size_t)(b * LL + l);
        const int c = h * HD + tx * 4;
        const float4 xs = *(const float4*)(g_xBCa + r * CONVD + c);
        float4 o;
        o.x = acc[i][0] + xs.x * dcoef;
        o.y = acc[i][1] + xs.y * dcoef;
        o.z = acc[i][2] + xs.z * dcoef;
        o.w = acc[i][3] + xs.w * dcoef;
        *(float4*)(g_y + r * DINNER + c) = o;
    }
}

// ------- g = y*silu(z); LayerNorm -> g_gn (tf32-rounded, k-PERMUTED store), float4 loads -------
__global__ void __launch_bounds__(192) ln_kernel(
    const float* __restrict__ nw, const float* __restrict__ nb)
{
    const int bl = blockIdx.x;
    const int tid = threadIdx.x;
    const int c = tid * 4;
    __shared__ float smu[6], sv[6];

    const float4 y4 = *(const float4*)(g_y + (size_t)bl * DINNER + c);
    const float4 z4 = *(const float4*)(g_z + (size_t)bl * DINNER + c);
    float v[4];
    v[0] = y4.x * (z4.x / (1.f + expf(-z4.x)));
    v[1] = y4.y * (z4.y / (1.f + expf(-z4.y)));
    v[2] = y4.z * (z4.z / (1.f + expf(-z4.z)));
    v[3] = y4.w * (z4.w / (1.f + expf(-z4.w)));
    float s = v[0] + v[1] + v[2] + v[3];
    float s2 = v[0] * v[0] + v[1] * v[1] + v[2] * v[2] + v[3] * v[3];
#pragma unroll
    for (int o = 16; o > 0; o >>= 1) {
        s += __shfl_xor_sync(0xffffffffu, s, o);
        s2 += __shfl_xor_sync(0xffffffffu, s2, o);
    }
    const int w = tid >> 5;
    if ((tid & 31) == 0) { smu[w] = s; sv[w] = s2; }
    __syncthreads();
    float ts = 0.f, ts2 = 0.f;
#pragma unroll
    for (int i = 0; i < 6; i++) { ts += smu[i]; ts2 += sv[i]; }

    const float mu = ts * (1.f / (float)DINNER);
    const float var = ts2 * (1.f / (float)DINNER) - mu * mu;
    const float rstd = rsqrtf(var + 1e-5f);
    const float4 w4 = *(const float4*)(nw + c);
    const float4 b4 = *(const float4*)(nb + c);
    const float wv[4] = {w4.x, w4.y, w4.z, w4.w};
    const float bv[4] = {b4.x, b4.y, b4.z, b4.w};
#pragma unroll
    for (int i = 0; i < 4; i++) {
        const int cc = c + i;
        const float o = (v[i] - mu) * rstd * wv[i] + bv[i];
        const int pc = (cc & ~15) | ((cc & 3) << 2) | ((cc >> 2) & 3);
        g_gn[(size_t)bl * DINNER + pc] = __uint_as_float(f2tf32(o));
    }
}

// ---------------- launch ----------------
extern "C" void kernel_launch(void* const* d_in, const int* in_sizes, int n_in,
                              void* d_out, int out_size)
{
    const float* x    = (const float*)d_in[0];   // [BL, 384]
    const float* win  = (const float*)d_in[1];   // [1676, 384]
    const float* cw   = (const float*)d_in[2];   // [896, 1, 3, 3]
    const float* cb   = (const float*)d_in[3];   // [896]
    const float* dtb  = (const float*)d_in[4];   // [12]
    const float* alog = (const float*)d_in[5];   // [768]
    const float* Dp   = (const float*)d_in[6];   // [12]
    const float* nw   = (const float*)d_in[7];   // [768]
    const float* nb   = (const float*)d_in[8];   // [768]
    const float* wout = (const float*)d_in[9];   // [384, 768]
    float* out = (float*)d_out;                  // [BL, 384]

    cudaFuncSetAttribute(gemm_mma<DMODEL, 0>,
                         cudaFuncAttributeMaxDynamicSharedMemorySize, GEMM_DSMEM);
    cudaFuncSetAttribute(gemm_mma<DINNER, 1>,
                         cudaFuncAttributeMaxDynamicSharedMemorySize, GEMM_DSMEM);

    float* xcvt;    cudaGetSymbolAddress((void**)&xcvt, g_xcvt);
    float* wincvt;  cudaGetSymbolAddress((void**)&wincvt, g_wincvt);
    float* woutcvt; cudaGetSymbolAddress((void**)&woutcvt, g_woutcvt);

    // prep: round/permute in-proj inputs, zero h_state, negA + weight transpose
    cvt_perm_kernel<<<(BL * DMODEL / 16 + 255) / 256, 256>>>(x, xcvt, BL * DMODEL / 16);
    cvt_perm_kernel<<<(DPROJ * DMODEL / 16 + 255) / 256, 256>>>(win, wincvt, DPROJ * DMODEL / 16);
    zero_hstate<<<384, 256>>>();
    prep_kernel<<<(9 * CONVD + 255) / 256, 256>>>(alog, cw);
    // in-proj GEMM (256x128 tiles) + split epilogue
    gemm_mma<DMODEL, 0><<<dim3(14, 98), 512, GEMM_DSMEM>>>(nullptr, dtb, DPROJ);
    // depthwise conv + silu (float4)
    conv_kernel<<<BL, 224>>>(cb);
    // round+permute out-proj weight (independent)
    cvt_perm_kernel<<<(DMODEL * DINNER / 16 + 255) / 256, 256>>>(wout, woutcvt, DMODEL * DINNER / 16);
    // fused dx + pool (float4)
    dxpool_kernel<<<BL, 192>>>();
    // split-K batched state GEMM
    hstate_kernel<<<dim3(7, 12, 8), 256>>>();
    // Ch + D*x -> y
    ch_kernel<<<dim3(49, 12, 8), 256>>>(Dp);
    // gate + LayerNorm (float4 loads, permuted tf32 store)
    ln_kernel<<<BL, 192>>>(nw, nb);
    // out-proj GEMM (256x128 tiles)
    gemm_mma<DINNER, 1><<<dim3(3, 98), 512, GEMM_DSMEM>>>(out, nullptr, DMODEL);
}

// round 13
// speedup vs baseline: 1.1012x; 1.1012x over previous
#include <cuda_runtime.h>
#include <math.h>
#include <stdint.h>

#define BQ 8
#define HH 56
#define WW 56
#define LL 3136          // HH*WW
#define BL 25088         // BQ*LL
#define DMODEL 384
#define DINNER 768
#define NH 12
#define HD 64
#define DST 64
#define CONVD 896        // DINNER + 2*DSTATE
#define DPROJ 1676       // 2*DINNER + 2*DSTATE + NH

// ---------------- scratch (device globals: allocation-free contract) ----------------
__device__ float g_z[(size_t)BL * DINNER];      // z branch
__device__ float g_xBC[(size_t)BL * CONVD];     // pre-conv xBC
__device__ float g_dt[(size_t)BL * NH];         // softplus(dt + bias)
__device__ float g_xBCa[(size_t)BL * CONVD];    // post conv+silu  (xs | B | C)
__device__ float g_y[(size_t)BL * DINNER];      // y (ch output)
__device__ float g_Bp[(size_t)BL * DST];        // transpose-pooled B
__device__ float g_hstate[BQ * NH * DST * HD];  // per (b,h) 64x64 state
__device__ float g_gn[(size_t)BL * DINNER];     // post-LN (tf32-rounded, k-permuted)
__device__ float g_xcvt[(size_t)BL * DMODEL];   // tf32-rounded, k-permuted x
__device__ float g_wincvt[(size_t)DPROJ * DMODEL];   // tf32, k-permuted in_proj_w
__device__ float g_woutcvt[(size_t)DMODEL * DINNER]; // tf32, k-permuted out_proj_w
__device__ float g_negA[DINNER];                // -exp(A_log)
__device__ float g_cwT[9 * CONVD];              // conv weights transposed [tap][c]

__device__ __forceinline__ uint32_t f2tf32(float f) {
    uint32_t u;
    asm("cvt.rna.tf32.f32 %0, %1;" : "=r"(u) : "f"(f));
    return u;
}
__device__ __forceinline__ uint32_t smem_u32(const void* p) {
    uint32_t a;
    asm("{ .reg .u64 t; cvta.to.shared.u64 t, %1; cvt.u32.u64 %0, t; }"
        : "=r"(a) : "l"(p));
    return a;
}
__device__ __forceinline__ void mma_tf32(float c[4], float a0, float a1,
                                         float a2, float a3,
                                         float b0, float b1) {
    asm volatile(
        "mma.sync.aligned.m16n8k8.row.col.f32.tf32.tf32.f32 "
        "{%0,%1,%2,%3}, {%4,%5,%6,%7}, {%8,%9}, {%0,%1,%2,%3};"
        : "+f"(c[0]), "+f"(c[1]), "+f"(c[2]), "+f"(c[3])
        : "r"(__float_as_uint(a0)), "r"(__float_as_uint(a1)),
          "r"(__float_as_uint(a2)), "r"(__float_as_uint(a3)),
          "r"(__float_as_uint(b0)), "r"(__float_as_uint(b1)));
}
__device__ __forceinline__ void cpa16(uint32_t dst, const void* src, int srcbytes) {
    asm volatile("cp.async.cg.shared.global [%0], [%1], 16, %2;"
                 :: "r"(dst), "l"(src), "r"(srcbytes) : "memory");
}
__device__ __forceinline__ void cpa_commit() {
    asm volatile("cp.async.commit_group;" ::: "memory");
}
__device__ __forceinline__ void cpa_wait2() {
    asm volatile("cp.async.wait_group 2;" ::: "memory");
}

// ------- tf32-round + k-permute: within each 16-float group, pos = ((k&3)<<2)|(k>>2) -------
__global__ void __launch_bounds__(256) cvt_perm_kernel(
    const float* __restrict__ src, float* __restrict__ dst, int ngroups)
{
    const int g = blockIdx.x * 256 + threadIdx.x;
    if (g >= ngroups) return;
    const float4* s = (const float4*)src + (size_t)g * 4;
    float4 v0 = s[0], v1 = s[1], v2 = s[2], v3 = s[3];
    uint4 o0, o1, o2, o3;
    o0.x = f2tf32(v0.x); o0.y = f2tf32(v1.x); o0.z = f2tf32(v2.x); o0.w = f2tf32(v3.x);
    o1.x = f2tf32(v0.y); o1.y = f2tf32(v1.y); o1.z = f2tf32(v2.y); o1.w = f2tf32(v3.y);
    o2.x = f2tf32(v0.z); o2.y = f2tf32(v1.z); o2.z = f2tf32(v2.z); o2.w = f2tf32(v3.z);
    o3.x = f2tf32(v0.w); o3.y = f2tf32(v1.w); o3.z = f2tf32(v2.w); o3.w = f2tf32(v3.w);
    uint4* d = (uint4*)dst + (size_t)g * 4;
    d[0] = o0; d[1] = o1; d[2] = o2; d[3] = o3;
}

// ---------------- prep: -exp(A_log) + conv-weight transpose [c][9] -> [tap][c] ----------------
__global__ void prep_kernel(const float* __restrict__ A_log, const float* __restrict__ cw)
{
    const int i = threadIdx.x + blockIdx.x * 256;
    if (i < DINNER) g_negA[i] = -expf(A_log[i]);
    if (i < 9 * CONVD) {
        const int c = i / 9, t = i - c * 9;
        g_cwT[t * CONVD + c] = cw[i];
    }
}

// ============ tf32 mma.sync GEMM, 128x128 CTA, k-permuted LDS.128 (R10 proven config) ============
#define STAGEB (128 * 16 * 4)
#define GSTAGES 4
#define GEMM_DSMEM (2 * GSTAGES * STAGEB + 128)

template <int KDIM, int MODE>
__global__ void __launch_bounds__(256) gemm_mma(
    float* __restrict__ out, const float* __restrict__ dt_bias, int N)
{
    extern __shared__ char raw_smem[];
    const uint32_t raw_u = smem_u32(raw_smem);
    const uint32_t dsm_u = (raw_u + 127u) & ~127u;
    char* dsm = raw_smem + (dsm_u - raw_u);

    const int tid = threadIdx.x;
    const int lane = tid & 31;
    const int warp = tid >> 5;
    const int bm = blockIdx.y * 128;
    const int bn = blockIdx.x * 128;
    const int wm = (warp >> 2) * 64;
    const int wn = (warp & 3) * 32;
    const int mrow = lane >> 2;
    const int kc = (lane & 3) * 4;

    const float* Ap = (MODE == 0) ? g_xcvt : g_gn;
    const float* Bp = (MODE == 0) ? g_wincvt : g_woutcvt;

    float acc[4][4][4];
#pragma unroll
    for (int i = 0; i < 4; i++)
#pragma unroll
        for (int j = 0; j < 4; j++)
#pragma unroll
            for (int r = 0; r < 4; r++) acc[i][j][r] = 0.f;

    auto issue_stage = [&](int kt, int s) {
        const int k0 = kt * 16;
        const uint32_t abase = dsm_u + s * STAGEB;
        const uint32_t bbase = dsm_u + GSTAGES * STAGEB + s * STAGEB;
#pragma unroll
        for (int i = 0; i < 2; i++) {
            const int c = tid + i * 256;
            const int row = c >> 2;
            const int q = c & 3;
            const uint32_t soff = (uint32_t)(row * 64 + q * 16);
            cpa16(abase + soff, Ap + (size_t)(bm + row) * KDIM + k0 + q * 4, 16);
            const int nb = bn + row;
            const int okB = (MODE == 1 || nb < N) ? 16 : 0;
            const int nbs = (MODE == 1 || nb < N) ? nb : (N - 1);
            cpa16(bbase + soff, Bp + (size_t)nbs * KDIM + k0 + q * 4, okB);
        }
    };

    constexpr int KT = KDIM / 16;
#pragma unroll
    for (int p = 0; p < GSTAGES - 1; p++) {
        issue_stage(p, p);
        cpa_commit();
    }

#pragma unroll 1
    for (int kt = 0; kt < KT; kt++) {
        const int s = kt & (GSTAGES - 1);
        cpa_wait2();
        __syncthreads();

        const float* Asb = (const float*)(dsm + s * STAGEB);
        const float* Bsb = (const float*)(dsm + GSTAGES * STAGEB + s * STAGEB);

        float4 bf[4];
#pragma unroll
        for (int j = 0; j < 4; j++) {
            const int n = wn + j * 8 + mrow;
            bf[j] = *(const float4*)&Bsb[n * 16 + kc];
        }
#pragma unroll
        for (int i = 0; i < 4; i++) {
            const int m = wm + i * 16 + mrow;
            float4 aL = *(const float4*)&Asb[m * 16 + kc];
            float4 aH = *(const float4*)&Asb[(m + 8) * 16 + kc];
#pragma unroll
            for (int j = 0; j < 4; j++) {
                mma_tf32(acc[i][j], aL.x, aH.x, aL.y, aH.y, bf[j].x, bf[j].y);
                mma_tf32(acc[i][j], aL.z, aH.z, aL.w, aH.w, bf[j].z, bf[j].w);
            }
        }

        const int nk = kt + GSTAGES - 1;
        if (nk < KT) issue_stage(nk, nk & (GSTAGES - 1));
        cpa_commit();
    }

    // ---- epilogue: fragment (r, r+1) pairs adjacent in n -> STG.64 ----
#pragma unroll
    for (int i = 0; i < 4; i++) {
        const int m0 = bm + wm + i * 16 + mrow;     // rows m0 and m0+8
#pragma unroll
        for (int j = 0; j < 4; j++) {
            const int n = bn + wn + j * 8 + (lane & 3) * 2;
            const float2 p0 = make_float2(acc[i][j][0], acc[i][j][1]);
            const float2 p1 = make_float2(acc[i][j][2], acc[i][j][3]);
            if (MODE == 1) {
                *(float2*)(out + (size_t)m0 * DMODEL + n) = p0;
                *(float2*)(out + (size_t)(m0 + 8) * DMODEL + n) = p1;
            } else {
                if (n < DINNER) {
                    *(float2*)(g_z + (size_t)m0 * DINNER + n) = p0;
                    *(float2*)(g_z + (size_t)(m0 + 8) * DINNER + n) = p1;
                } else if (n < DINNER + CONVD) {
                    const int nn = n - DINNER;
                    *(float2*)(g_xBC + (size_t)m0 * CONVD + nn) = p0;
                    *(float2*)(g_xBC + (size_t)(m0 + 8) * CONVD + nn) = p1;
                } else {
                    const float vv[4] = {p0.x, p0.y, p1.x, p1.y};
#pragma unroll
                    for (int r = 0; r < 4; r++) {
                        const int ne = n + (r & 1);
                        if (ne < DPROJ) {
                            const int m = m0 + (r >> 1) * 8;
                            const int h = ne - (DINNER + CONVD);
                            const float t = vv[r] + dt_bias[h];
                            g_dt[(size_t)m * NH + h] =
                                (t > 20.f) ? t : log1pf(expf(t));
                        }
                    }
                }
            }
        }
    }
}

// ------- depthwise 3x3 conv + bias + silu, float4 channels (224 thr/block) -------
__global__ void __launch_bounds__(224) conv_kernel(const float* __restrict__ cb)
{
    const int c = threadIdx.x * 4;                  // 0..892
    const int bl = blockIdx.x;
    const int b = bl / LL;
    const int l = bl - b * LL;
    const int y = l / WW;
    const int x = l - y * WW;

    float4 acc = *(const float4*)(cb + c);
#pragma unroll
    for (int dy = -1; dy <= 1; dy++) {
        const int yy = y + dy;
        if (yy < 0 || yy >= HH) continue;
#pragma unroll
        for (int dx = -1; dx <= 1; dx++) {
            const int xx = x + dx;
            if (xx < 0 || xx >= WW) continue;
            const float4 v = *(const float4*)(g_xBC +
                ((size_t)(b * LL + yy * WW + xx)) * CONVD + c);
            const float4 w = *(const float4*)(g_cwT + ((dy + 1) * 3 + (dx + 1)) * CONVD + c);
            acc.x = fmaf(v.x, w.x, acc.x);
            acc.y = fmaf(v.y, w.y, acc.y);
            acc.z = fmaf(v.z, w.z, acc.z);
            acc.w = fmaf(v.w, w.w, acc.w);
        }
    }
    float4 o;
    o.x = acc.x / (1.f + expf(-acc.x));
    o.y = acc.y / (1.f + expf(-acc.y));
    o.z = acc.z / (1.f + expf(-acc.z));
    o.w = acc.w / (1.f + expf(-acc.w));
    *(float4*)(g_xBCa + (size_t)bl * CONVD + c) = o;
}

// ---- transpose-pooled B:  Bp[l', s] = sum_{l in N(l')} B[l, s] / cnt(l) ----
// (3x3 neighborhoods are symmetric; cnt(l) = the NEIGHBOR's own divisor)
__global__ void __launch_bounds__(128) bpool_kernel()
{
    const int tx = threadIdx.x & 15;        // float4 group within 64 channels
    const int bl = blockIdx.x * 8 + (threadIdx.x >> 4);
    const int b = bl / LL;
    const int l = bl - b * LL;
    const int y = l / WW;
    const int x = l - y * WW;

    float4 s = make_float4(0.f, 0.f, 0.f, 0.f);
#pragma unroll
    for (int dy = -1; dy <= 1; dy++) {
        const int yy = y + dy;
        if (yy < 0 || yy >= HH) continue;
#pragma unroll
        for (int dx = -1; dx <= 1; dx++) {
            const int xx = x + dx;
            if (xx < 0 || xx >= WW) continue;
            // neighbor's own count
            const int cy = min(yy + 1, HH - 1) - max(yy - 1, 0) + 1;
            const int cx = min(xx + 1, WW - 1) - max(xx - 1, 0) + 1;
            const float w = 1.f / (float)(cy * cx);
            const float4 v = *(const float4*)(g_xBCa +
                ((size_t)(b * LL + yy * WW + xx)) * CONVD + DINNER + tx * 4);
            s.x = fmaf(v.x, w, s.x);
            s.y = fmaf(v.y, w, s.y);
            s.z = fmaf(v.z, w, s.z);
            s.w = fmaf(v.w, w, s.w);
        }
    }
    *(float4*)(g_Bp + (size_t)bl * DST + tx * 4) = s;
}

// ---------------- zero h_state ----------------
__global__ void zero_hstate()
{
    const int i = blockIdx.x * 256 + threadIdx.x;
    ((float4*)g_hstate)[i] = make_float4(0.f, 0.f, 0.f, 0.f);
}

// ---- h_state[b,h,s,d] += sum_l Bp[b,l,s] * (xBCa[b,l,h*64+d] * dt[b,l,h])  (split-K over L) ----
__global__ void __launch_bounds__(256) hstate_kernel()
{
    const int b = blockIdx.z;
    const int h = blockIdx.y;
    const int l0 = blockIdx.x * 448;

    __shared__ __align__(16) float Bs[16][64];
    __shared__ __align__(16) float Ds[16][64];

    const int tid = threadIdx.x;
    const int ty = tid >> 4, tx = tid & 15;
    const int lr = tid >> 4;
    const int f4 = (tid & 15) * 4;

    float acc[4][4];
#pragma unroll
    for (int i = 0; i < 4; i++)
#pragma unroll
        for (int j = 0; j < 4; j++) acc[i][j] = 0.f;

    for (int lt = 0; lt < 448; lt += 16) {
        const int l = l0 + lt + lr;
        const size_t rb = (size_t)(b * LL + l);
        *(float4*)&Bs[lr][f4] = *(const float4*)(g_Bp + rb * DST + f4);
        const float dtv = g_dt[rb * NH + h];
        float4 u = *(const float4*)(g_xBCa + rb * CONVD + h * HD + f4);
        u.x *= dtv; u.y *= dtv; u.z *= dtv; u.w *= dtv;
        *(float4*)&Ds[lr][f4] = u;
        __syncthreads();
#pragma unroll
        for (int kk = 0; kk < 16; kk++) {
            float4 a = *(const float4*)&Bs[kk][ty * 4];
            float4 d = *(const float4*)&Ds[kk][tx * 4];
            float av[4] = {a.x, a.y, a.z, a.w};
            float dv[4] = {d.x, d.y, d.z, d.w};
#pragma unroll
            for (int i = 0; i < 4; i++)
#pragma unroll
                for (int j = 0; j < 4; j++)
                    acc[i][j] = fmaf(av[i], dv[j], acc[i][j]);
        }
        __syncthreads();
    }

    float* hp = g_hstate + (size_t)(b * NH + h) * DST * HD;
#pragma unroll
    for (int i = 0; i < 4; i++)
#pragma unroll
        for (int j = 0; j < 4; j++)
            atomicAdd(&hp[(ty * 4 + i) * HD + tx * 4 + j], acc[i][j]);
}

// ---- y[b,l,h,d] = sum_s C[b,l,s] * (hstate[b,h,s,d]*negA[h*64+d]) + xs * D[h] ----
__global__ void __launch_bounds__(256) ch_kernel(const float* __restrict__ Dp)
{
    const int b = blockIdx.z;
    const int h = blockIdx.y;
    const int l0 = blockIdx.x * 64;

    __shared__ __align__(16) float Hs[64][64];   // [s][d] (negA-scaled)
    __shared__ __align__(16) float Cs[64][68];   // [s][l] (transposed)

    const int tid = threadIdx.x;
    const int ty = tid >> 4, tx = tid & 15;

    {
        const float4* hsrc = (const float4*)(g_hstate + (size_t)(b * NH + h) * DST * HD);
        float4* hdst = (float4*)Hs;
#pragma unroll
        for (int i = 0; i < 4; i++) {
            const int idx = tid + i * 256;
            const int dq = (idx & 15) * 4;
            const float4 na = *(const float4*)(g_negA + h * HD + dq);
            float4 v = hsrc[idx];
            v.x *= na.x; v.y *= na.y; v.z *= na.z; v.w *= na.w;
            hdst[idx] = v;
        }
    }
    {
        const int lr = tid >> 2;
        const int base = (tid & 3) * 4;
        const float* crow = g_xBCa + (size_t)(b * LL + l0 + lr) * CONVD + DINNER + DST;
#pragma unroll
        for (int it = 0; it < 4; it++) {
            const int sq = base + it * 16;
            float4 v = *(const float4*)(crow + sq);
            Cs[sq + 0][lr] = v.x; Cs[sq + 1][lr] = v.y;
            Cs[sq + 2][lr] = v.z; Cs[sq + 3][lr] = v.w;
        }
    }
    __syncthreads();

    float acc[4][4];
#pragma unroll
    for (int i = 0; i < 4; i++)
#pragma unroll
        for (int j = 0; j < 4; j++) acc[i][j] = 0.f;

#pragma unroll 16
    for (int s = 0; s < 64; s++) {
        float4 a = *(const float4*)&Cs[s][ty * 4];
        float4 hv = *(const float4*)&Hs[s][tx * 4];
        float av[4] = {a.x, a.y, a.z, a.w};
        float hvv[4] = {hv.x, hv.y, hv.z, hv.w};
#pragma unroll
        for (int i = 0; i < 4; i++)
#pragma unroll
            for (int j = 0; j < 4; j++)
                acc[i][j] = fmaf(av[i], hvv[j], acc[i][j]);
    }

    const float dcoef = Dp[h];
#pragma unroll
    for (int i = 0; i < 4; i++) {
        const int l = l0 + ty * 4 + i;
        const size_t r = (size_t)(b * LL + l);
        const int c = h * HD + tx * 4;
        const float4 xs = *(const float4*)(g_xBCa + r * CONVD + c);
        float4 o;
        o.x = acc[i][0] + xs.x * dcoef;
        o.y = acc[i][1] + xs.y * dcoef;
        o.z = acc[i][2] + xs.z * dcoef;
        o.w = acc[i][3] + xs.w * dcoef;
        *(float4*)(g_y + r * DINNER + c) = o;
    }
}

// ------- g = y*silu(z); LayerNorm -> g_gn (tf32-rounded, k-PERMUTED store), float4 loads -------
__global__ void __launch_bounds__(192) ln_kernel(
    const float* __restrict__ nw, const float* __restrict__ nb)
{
    const int bl = blockIdx.x;
    const int tid = threadIdx.x;
    const int c = tid * 4;
    __shared__ float smu[6], sv[6];

    const float4 y4 = *(const float4*)(g_y + (size_t)bl * DINNER + c);
    const float4 z4 = *(const float4*)(g_z + (size_t)bl * DINNER + c);
    float v[4];
    v[0] = y4.x * (z4.x / (1.f + expf(-z4.x)));
    v[1] = y4.y * (z4.y / (1.f + expf(-z4.y)));
    v[2] = y4.z * (z4.z / (1.f + expf(-z4.z)));
    v[3] = y4.w * (z4.w / (1.f + expf(-z4.w)));
    float s = v[0] + v[1] + v[2] + v[3];
    float s2 = v[0] * v[0] + v[1] * v[1] + v[2] * v[2] + v[3] * v[3];
#pragma unroll
    for (int o = 16; o > 0; o >>= 1) {
        s += __shfl_xor_sync(0xffffffffu, s, o);
        s2 += __shfl_xor_sync(0xffffffffu, s2, o);
    }
    const int w = tid >> 5;
    if ((tid & 31) == 0) { smu[w] = s; sv[w] = s2; }
    __syncthreads();
    float ts = 0.f, ts2 = 0.f;
#pragma unroll
    for (int i = 0; i < 6; i++) { ts += smu[i]; ts2 += sv[i]; }

    const float mu = ts * (1.f / (float)DINNER);
    const float var = ts2 * (1.f / (float)DINNER) - mu * mu;
    const float rstd = rsqrtf(var + 1e-5f);
    const float4 w4 = *(const float4*)(nw + c);
    const float4 b4 = *(const float4*)(nb + c);
    const float wv[4] = {w4.x, w4.y, w4.z, w4.w};
    const float bv[4] = {b4.x, b4.y, b4.z, b4.w};
#pragma unroll
    for (int i = 0; i < 4; i++) {
        const int cc = c + i;
        const float o = (v[i] - mu) * rstd * wv[i] + bv[i];
        const int pc = (cc & ~15) | ((cc & 3) << 2) | ((cc >> 2) & 3);
        g_gn[(size_t)bl * DINNER + pc] = __uint_as_float(f2tf32(o));
    }
}

// ---------------- launch ----------------
extern "C" void kernel_launch(void* const* d_in, const int* in_sizes, int n_in,
                              void* d_out, int out_size)
{
    const float* x    = (const float*)d_in[0];   // [BL, 384]
    const float* win  = (const float*)d_in[1];   // [1676, 384]
    const float* cw   = (const float*)d_in[2];   // [896, 1, 3, 3]
    const float* cb   = (const float*)d_in[3];   // [896]
    const float* dtb  = (const float*)d_in[4];   // [12]
    const float* alog = (const float*)d_in[5];   // [768]
    const float* Dp   = (const float*)d_in[6];   // [12]
    const float* nw   = (const float*)d_in[7];   // [768]
    const float* nb   = (const float*)d_in[8];   // [768]
    const float* wout = (const float*)d_in[9];   // [384, 768]
    float* out = (float*)d_out;                  // [BL, 384]

    cudaFuncSetAttribute(gemm_mma<DMODEL, 0>,
                         cudaFuncAttributeMaxDynamicSharedMemorySize, GEMM_DSMEM);
    cudaFuncSetAttribute(gemm_mma<DINNER, 1>,
                         cudaFuncAttributeMaxDynamicSharedMemorySize, GEMM_DSMEM);

    float* xcvt;    cudaGetSymbolAddress((void**)&xcvt, g_xcvt);
    float* wincvt;  cudaGetSymbolAddress((void**)&wincvt, g_wincvt);
    float* woutcvt; cudaGetSymbolAddress((void**)&woutcvt, g_woutcvt);

    // prep: round/permute in-proj inputs, zero h_state, negA + weight transpose
    cvt_perm_kernel<<<(BL * DMODEL / 16 + 255) / 256, 256>>>(x, xcvt, BL * DMODEL / 16);
    cvt_perm_kernel<<<(DPROJ * DMODEL / 16 + 255) / 256, 256>>>(win, wincvt, DPROJ * DMODEL / 16);
    zero_hstate<<<384, 256>>>();
    prep_kernel<<<(9 * CONVD + 255) / 256, 256>>>(alog, cw);
    // in-proj GEMM (128x128, R10 config) + split epilogue
    gemm_mma<DMODEL, 0><<<dim3(14, 196), 256, GEMM_DSMEM>>>(nullptr, dtb, DPROJ);
    // depthwise conv + silu (float4)
    conv_kernel<<<BL, 224>>>(cb);
    // round+permute out-proj weight (independent)
    cvt_perm_kernel<<<(DMODEL * DINNER / 16 + 255) / 256, 256>>>(wout, woutcvt, DMODEL * DINNER / 16);
    // transpose-pooled B (replaces 768-channel dxpool)
    bpool_kernel<<<BL / 8, 128>>>();
    // split-K batched state GEMM (dt*xs on the fly)
    hstate_kernel<<<dim3(7, 12, 8), 256>>>();
    // Ch (negA folded into Hs) + D*x -> y
    ch_kernel<<<dim3(49, 12, 8), 256>>>(Dp);
    // gate + LayerNorm (float4 loads, permuted tf32 store)
    ln_kernel<<<BL, 192>>>(nw, nb);
    // out-proj GEMM (N = 384 = 3 x 128 tiles)
    gemm_mma<DINNER, 1><<<dim3(3, 196), 256, GEMM_DSMEM>>>(out, nullptr, DMODEL);
}

// round 14
// speedup vs baseline: 1.1272x; 1.0236x over previous
#include <cuda_runtime.h>
#include <math.h>
#include <stdint.h>

#define BQ 8
#define HH 56
#define WW 56
#define LL 3136          // HH*WW
#define BL 25088         // BQ*LL
#define DMODEL 384
#define DINNER 768
#define NH 12
#define HD 64
#define DST 64
#define CONVD 896        // DINNER + 2*DSTATE
#define DPROJ 1676       // 2*DINNER + 2*DSTATE + NH

// ---------------- scratch (device globals: allocation-free contract) ----------------
__device__ float g_z[(size_t)BL * DINNER];      // z branch
__device__ float g_xBC[(size_t)BL * CONVD];     // pre-conv xBC
__device__ float g_dt[(size_t)BL * NH];         // softplus(dt + bias)
__device__ float g_xBCa[(size_t)BL * CONVD];    // post conv+silu  (xs | B | C)
__device__ float g_y[(size_t)BL * DINNER];      // y (ch output)
__device__ float g_Bp[(size_t)BL * DST];        // transpose-pooled B
__device__ float g_hstate[BQ * NH * DST * HD];  // per (b,h) 64x64 state
__device__ float g_gn[(size_t)BL * DINNER];     // post-LN (tf32-rounded, k-permuted)
__device__ float g_xcvt[(size_t)BL * DMODEL];   // tf32-rounded, k-permuted x
__device__ float g_wincvt[(size_t)DPROJ * DMODEL];   // tf32, k-permuted in_proj_w
__device__ float g_woutcvt[(size_t)DMODEL * DINNER]; // tf32, k-permuted out_proj_w
__device__ float g_negA[DINNER];                // -exp(A_log)
__device__ float g_cwT[9 * CONVD];              // conv weights transposed [tap][c]

__device__ __forceinline__ uint32_t f2tf32(float f) {
    uint32_t u;
    asm("cvt.rna.tf32.f32 %0, %1;" : "=r"(u) : "f"(f));
    return u;
}
__device__ __forceinline__ uint32_t smem_u32(const void* p) {
    uint32_t a;
    asm("{ .reg .u64 t; cvta.to.shared.u64 t, %1; cvt.u32.u64 %0, t; }"
        : "=r"(a) : "l"(p));
    return a;
}
__device__ __forceinline__ void mma_tf32(float c[4], float a0, float a1,
                                         float a2, float a3,
                                         float b0, float b1) {
    asm volatile(
        "mma.sync.aligned.m16n8k8.row.col.f32.tf32.tf32.f32 "
        "{%0,%1,%2,%3}, {%4,%5,%6,%7}, {%8,%9}, {%0,%1,%2,%3};"
        : "+f"(c[0]), "+f"(c[1]), "+f"(c[2]), "+f"(c[3])
        : "r"(__float_as_uint(a0)), "r"(__float_as_uint(a1)),
          "r"(__float_as_uint(a2)), "r"(__float_as_uint(a3)),
          "r"(__float_as_uint(b0)), "r"(__float_as_uint(b1)));
}
__device__ __forceinline__ void cpa16(uint32_t dst, const void* src, int srcbytes) {
    asm volatile("cp.async.cg.shared.global [%0], [%1], 16, %2;"
                 :: "r"(dst), "l"(src), "r"(srcbytes) : "memory");
}
__device__ __forceinline__ void cpa_commit() {
    asm volatile("cp.async.commit_group;" ::: "memory");
}
__device__ __forceinline__ void cpa_wait2() {
    asm volatile("cp.async.wait_group 2;" ::: "memory");
}

// ------- tf32-round + k-permute: within each 16-float group, pos = ((k&3)<<2)|(k>>2) -------
__global__ void __launch_bounds__(256) cvt_perm_kernel(
    const float* __restrict__ src, float* __restrict__ dst, int ngroups)
{
    const int g = blockIdx.x * 256 + threadIdx.x;
    if (g >= ngroups) return;
    const float4* s = (const float4*)src + (size_t)g * 4;
    float4 v0 = s[0], v1 = s[1], v2 = s[2], v3 = s[3];
    uint4 o0, o1, o2, o3;
    o0.x = f2tf32(v0.x); o0.y = f2tf32(v1.x); o0.z = f2tf32(v2.x); o0.w = f2tf32(v3.x);
    o1.x = f2tf32(v0.y); o1.y = f2tf32(v1.y); o1.z = f2tf32(v2.y); o1.w = f2tf32(v3.y);
    o2.x = f2tf32(v0.z); o2.y = f2tf32(v1.z); o2.z = f2tf32(v2.z); o2.w = f2tf32(v3.z);
    o3.x = f2tf32(v0.w); o3.y = f2tf32(v1.w); o3.z = f2tf32(v2.w); o3.w = f2tf32(v3.w);
    uint4* d = (uint4*)dst + (size_t)g * 4;
    d[0] = o0; d[1] = o1; d[2] = o2; d[3] = o3;
}

// ---------------- prep: -exp(A_log) + conv-weight transpose [c][9] -> [tap][c] ----------------
__global__ void prep_kernel(const float* __restrict__ A_log, const float* __restrict__ cw)
{
    const int i = threadIdx.x + blockIdx.x * 256;
    if (i < DINNER) g_negA[i] = -expf(A_log[i]);
    if (i < 9 * CONVD) {
        const int c = i / 9, t = i - c * 9;
        g_cwT[t * CONVD + c] = cw[i];
    }
}

// ============ tf32 mma.sync GEMM, 128x128 CTA, k-permuted LDS.128 (R10 proven config) ============
#define STAGEB (128 * 16 * 4)
#define GSTAGES 4
#define GEMM_DSMEM (2 * GSTAGES * STAGEB + 128)

template <int KDIM, int MODE>
__global__ void __launch_bounds__(256) gemm_mma(
    float* __restrict__ out, const float* __restrict__ dt_bias, int N)
{
    extern __shared__ char raw_smem[];
    const uint32_t raw_u = smem_u32(raw_smem);
    const uint32_t dsm_u = (raw_u + 127u) & ~127u;
    char* dsm = raw_smem + (dsm_u - raw_u);

    const int tid = threadIdx.x;
    const int lane = tid & 31;
    const int warp = tid >> 5;
    const int bm = blockIdx.y * 128;
    const int bn = blockIdx.x * 128;
    const int wm = (warp >> 2) * 64;
    const int wn = (warp & 3) * 32;
    const int mrow = lane >> 2;
    const int kc = (lane & 3) * 4;

    const float* Ap = (MODE == 0) ? g_xcvt : g_gn;
    const float* Bp = (MODE == 0) ? g_wincvt : g_woutcvt;

    float acc[4][4][4];
#pragma unroll
    for (int i = 0; i < 4; i++)
#pragma unroll
        for (int j = 0; j < 4; j++)
#pragma unroll
            for (int r = 0; r < 4; r++) acc[i][j][r] = 0.f;

    auto issue_stage = [&](int kt, int s) {
        const int k0 = kt * 16;
        const uint32_t abase = dsm_u + s * STAGEB;
        const uint32_t bbase = dsm_u + GSTAGES * STAGEB + s * STAGEB;
#pragma unroll
        for (int i = 0; i < 2; i++) {
            const int c = tid + i * 256;
            const int row = c >> 2;
            const int q = c & 3;
            const uint32_t soff = (uint32_t)(row * 64 + q * 16);
            cpa16(abase + soff, Ap + (size_t)(bm + row) * KDIM + k0 + q * 4, 16);
            const int nb = bn + row;
            const int okB = (MODE == 1 || nb < N) ? 16 : 0;
            const int nbs = (MODE == 1 || nb < N) ? nb : (N - 1);
            cpa16(bbase + soff, Bp + (size_t)nbs * KDIM + k0 + q * 4, okB);
        }
    };

    constexpr int KT = KDIM / 16;
#pragma unroll
    for (int p = 0; p < GSTAGES - 1; p++) {
        issue_stage(p, p);
        cpa_commit();
    }

#pragma unroll 1
    for (int kt = 0; kt < KT; kt++) {
        const int s = kt & (GSTAGES - 1);
        cpa_wait2();
        __syncthreads();

        const float* Asb = (const float*)(dsm + s * STAGEB);
        const float* Bsb = (const float*)(dsm + GSTAGES * STAGEB + s * STAGEB);

        float4 bf[4];
#pragma unroll
        for (int j = 0; j < 4; j++) {
            const int n = wn + j * 8 + mrow;
            bf[j] = *(const float4*)&Bsb[n * 16 + kc];
        }
#pragma unroll
        for (int i = 0; i < 4; i++) {
            const int m = wm + i * 16 + mrow;
            float4 aL = *(const float4*)&Asb[m * 16 + kc];
            float4 aH = *(const float4*)&Asb[(m + 8) * 16 + kc];
#pragma unroll
            for (int j = 0; j < 4; j++) {
                mma_tf32(acc[i][j], aL.x, aH.x, aL.y, aH.y, bf[j].x, bf[j].y);
                mma_tf32(acc[i][j], aL.z, aH.z, aL.w, aH.w, bf[j].z, bf[j].w);
            }
        }

        const int nk = kt + GSTAGES - 1;
        if (nk < KT) issue_stage(nk, nk & (GSTAGES - 1));
        cpa_commit();
    }

    // ---- epilogue: fragment (r, r+1) pairs adjacent in n -> STG.64 ----
#pragma unroll
    for (int i = 0; i < 4; i++) {
        const int m0 = bm + wm + i * 16 + mrow;     // rows m0 and m0+8
#pragma unroll
        for (int j = 0; j < 4; j++) {
            const int n = bn + wn + j * 8 + (lane & 3) * 2;
            const float2 p0 = make_float2(acc[i][j][0], acc[i][j][1]);
            const float2 p1 = make_float2(acc[i][j][2], acc[i][j][3]);
            if (MODE == 1) {
                *(float2*)(out + (size_t)m0 * DMODEL + n) = p0;
                *(float2*)(out + (size_t)(m0 + 8) * DMODEL + n) = p1;
            } else {
                if (n < DINNER) {
                    *(float2*)(g_z + (size_t)m0 * DINNER + n) = p0;
                    *(float2*)(g_z + (size_t)(m0 + 8) * DINNER + n) = p1;
                } else if (n < DINNER + CONVD) {
                    const int nn = n - DINNER;
                    *(float2*)(g_xBC + (size_t)m0 * CONVD + nn) = p0;
                    *(float2*)(g_xBC + (size_t)(m0 + 8) * CONVD + nn) = p1;
                } else {
                    const float vv[4] = {p0.x, p0.y, p1.x, p1.y};
#pragma unroll
                    for (int r = 0; r < 4; r++) {
                        const int ne = n + (r & 1);
                        if (ne < DPROJ) {
                            const int m = m0 + (r >> 1) * 8;
                            const int h = ne - (DINNER + CONVD);
                            const float t = vv[r] + dt_bias[h];
                            g_dt[(size_t)m * NH + h] =
                                (t > 20.f) ? t : log1pf(expf(t));
                        }
                    }
                }
            }
        }
    }
}

// ------- depthwise 3x3 conv + bias + silu, TWO x-adjacent outputs per thread -------
// Pairs (x0, x0+1) with x0 even never straddle a row (WW=56 even).
// 12 data LDG.128 + 9 weight LDG.128 per 2 outputs (was 18+18).
__global__ void __launch_bounds__(224) conv_kernel(const float* __restrict__ cb)
{
    const int c = threadIdx.x * 4;                  // 0..892
    const int bl0 = blockIdx.x * 2;
    const int b = bl0 / LL;
    const int l0 = bl0 - b * LL;
    const int y = l0 / WW;
    const int x0 = l0 - y * WW;                     // even, 0..54

    const float4 bias = *(const float4*)(cb + c);
    float4 a0 = bias, a1 = bias;

#pragma unroll
    for (int dy = -1; dy <= 1; dy++) {
        const int yy = y + dy;
        if (yy < 0 || yy >= HH) continue;
        const float* rowb = g_xBC + ((size_t)(b * LL + yy * WW)) * CONVD + c;
        float4 v[4];
#pragma unroll
        for (int t = 0; t < 4; t++) {
            const int xt = x0 - 1 + t;
            if (xt >= 0 && xt < WW)
                v[t] = *(const float4*)(rowb + (size_t)xt * CONVD);
            else
                v[t] = make_float4(0.f, 0.f, 0.f, 0.f);
        }
        const float* wb = g_cwT + (dy + 1) * 3 * CONVD + c;
        const float4 w0 = *(const float4*)(wb);
        const float4 w1 = *(const float4*)(wb + CONVD);
        const float4 w2 = *(const float4*)(wb + 2 * CONVD);
        // out at x0:  taps v[0],v[1],v[2];  out at x0+1: taps v[1],v[2],v[3]
        a0.x = fmaf(v[0].x, w0.x, fmaf(v[1].x, w1.x, fmaf(v[2].x, w2.x, a0.x)));
        a0.y = fmaf(v[0].y, w0.y, fmaf(v[1].y, w1.y, fmaf(v[2].y, w2.y, a0.y)));
        a0.z = fmaf(v[0].z, w0.z, fmaf(v[1].z, w1.z, fmaf(v[2].z, w2.z, a0.z)));
        a0.w = fmaf(v[0].w, w0.w, fmaf(v[1].w, w1.w, fmaf(v[2].w, w2.w, a0.w)));
        a1.x = fmaf(v[1].x, w0.x, fmaf(v[2].x, w1.x, fmaf(v[3].x, w2.x, a1.x)));
        a1.y = fmaf(v[1].y, w0.y, fmaf(v[2].y, w1.y, fmaf(v[3].y, w2.y, a1.y)));
        a1.z = fmaf(v[1].z, w0.z, fmaf(v[2].z, w1.z, fmaf(v[3].z, w2.z, a1.z)));
        a1.w = fmaf(v[1].w, w0.w, fmaf(v[2].w, w1.w, fmaf(v[3].w, w2.w, a1.w)));
    }
    float4 o0, o1;
    o0.x = a0.x / (1.f + expf(-a0.x));  o0.y = a0.y / (1.f + expf(-a0.y));
    o0.z = a0.z / (1.f + expf(-a0.z));  o0.w = a0.w / (1.f + expf(-a0.w));
    o1.x = a1.x / (1.f + expf(-a1.x));  o1.y = a1.y / (1.f + expf(-a1.y));
    o1.z = a1.z / (1.f + expf(-a1.z));  o1.w = a1.w / (1.f + expf(-a1.w));
    *(float4*)(g_xBCa + (size_t)bl0 * CONVD + c) = o0;
    *(float4*)(g_xBCa + (size_t)(bl0 + 1) * CONVD + c) = o1;
}

// ---- transpose-pooled B:  Bp[l', s] = sum_{l in N(l')} B[l, s] / cnt(l) ----
__global__ void __launch_bounds__(128) bpool_kernel()
{
    const int tx = threadIdx.x & 15;        // float4 group within 64 channels
    const int bl = blockIdx.x * 8 + (threadIdx.x >> 4);
    const int b = bl / LL;
    const int l = bl - b * LL;
    const int y = l / WW;
    const int x = l - y * WW;

    float4 s = make_float4(0.f, 0.f, 0.f, 0.f);
#pragma unroll
    for (int dy = -1; dy <= 1; dy++) {
        const int yy = y + dy;
        if (yy < 0 || yy >= HH) continue;
#pragma unroll
        for (int dx = -1; dx <= 1; dx++) {
            const int xx = x + dx;
            if (xx < 0 || xx >= WW) continue;
            const int cy = min(yy + 1, HH - 1) - max(yy - 1, 0) + 1;
            const int cx = min(xx + 1, WW - 1) - max(xx - 1, 0) + 1;
            const float w = 1.f / (float)(cy * cx);
            const float4 v = *(const float4*)(g_xBCa +
                ((size_t)(b * LL + yy * WW + xx)) * CONVD + DINNER + tx * 4);
            s.x = fmaf(v.x, w, s.x);
            s.y = fmaf(v.y, w, s.y);
            s.z = fmaf(v.z, w, s.z);
            s.w = fmaf(v.w, w, s.w);
        }
    }
    *(float4*)(g_Bp + (size_t)bl * DST + tx * 4) = s;
}

// ---------------- zero h_state ----------------
__global__ void zero_hstate()
{
    const int i = blockIdx.x * 256 + threadIdx.x;
    ((float4*)g_hstate)[i] = make_float4(0.f, 0.f, 0.f, 0.f);
}

// ---- h_state[b,h,s,d] += sum_l Bp[b,l,s] * (xBCa[b,l,h*64+d]*dt[b,l,h]); 2 heads/CTA ----
__global__ void __launch_bounds__(256) hstate_kernel()
{
    const int b = blockIdx.z;
    const int h0 = blockIdx.y * 2;
    const int l0 = blockIdx.x * 448;

    __shared__ __align__(16) float Bs[16][64];
    __shared__ __align__(16) float Ds[16][128];   // [l][head0 d | head1 d]

    const int tid = threadIdx.x;
    const int ty = tid >> 4, tx = tid & 15;
    const int lr = tid >> 4;
    const int f4 = (tid & 15) * 4;

    float acc0[4][4], acc1[4][4];
#pragma unroll
    for (int i = 0; i < 4; i++)
#pragma unroll
        for (int j = 0; j < 4; j++) { acc0[i][j] = 0.f; acc1[i][j] = 0.f; }

    for (int lt = 0; lt < 448; lt += 16) {
        const int l = l0 + lt + lr;
        const size_t rb = (size_t)(b * LL + l);
        *(float4*)&Bs[lr][f4] = *(const float4*)(g_Bp + rb * DST + f4);
        const float dt0 = g_dt[rb * NH + h0];
        const float dt1 = g_dt[rb * NH + h0 + 1];
        float4 u0 = *(const float4*)(g_xBCa + rb * CONVD + h0 * HD + f4);
        float4 u1 = *(const float4*)(g_xBCa + rb * CONVD + (h0 + 1) * HD + f4);
        u0.x *= dt0; u0.y *= dt0; u0.z *= dt0; u0.w *= dt0;
        u1.x *= dt1; u1.y *= dt1; u1.z *= dt1; u1.w *= dt1;
        *(float4*)&Ds[lr][f4] = u0;
        *(float4*)&Ds[lr][64 + f4] = u1;
        __syncthreads();
#pragma unroll
        for (int kk = 0; kk < 16; kk++) {
            float4 a = *(const float4*)&Bs[kk][ty * 4];
            float4 d0 = *(const float4*)&Ds[kk][tx * 4];
            float4 d1 = *(const float4*)&Ds[kk][64 + tx * 4];
            float av[4] = {a.x, a.y, a.z, a.w};
            float d0v[4] = {d0.x, d0.y, d0.z, d0.w};
            float d1v[4] = {d1.x, d1.y, d1.z, d1.w};
#pragma unroll
            for (int i = 0; i < 4; i++)
#pragma unroll
                for (int j = 0; j < 4; j++) {
                    acc0[i][j] = fmaf(av[i], d0v[j], acc0[i][j]);
                    acc1[i][j] = fmaf(av[i], d1v[j], acc1[i][j]);
                }
        }
        __syncthreads();
    }

    float* hp0 = g_hstate + (size_t)(b * NH + h0) * DST * HD;
    float* hp1 = g_hstate + (size_t)(b * NH + h0 + 1) * DST * HD;
#pragma unroll
    for (int i = 0; i < 4; i++)
#pragma unroll
        for (int j = 0; j < 4; j++) {
            atomicAdd(&hp0[(ty * 4 + i) * HD + tx * 4 + j], acc0[i][j]);
            atomicAdd(&hp1[(ty * 4 + i) * HD + tx * 4 + j], acc1[i][j]);
        }
}

// ---- y[b,l,h,d] = sum_s C[b,l,s] * (hstate[b,h,s,d]*negA[h*64+d]) + xs * D[h] ----
__global__ void __launch_bounds__(256) ch_kernel(const float* __restrict__ Dp)
{
    const int b = blockIdx.z;
    const int h = blockIdx.y;
    const int l0 = blockIdx.x * 64;

    __shared__ __align__(16) float Hs[64][64];   // [s][d] (negA-scaled)
    __shared__ __align__(16) float Cs[64][68];   // [s][l] (transposed)

    const int tid = threadIdx.x;
    const int ty = tid >> 4, tx = tid & 15;

    {
        const float4* hsrc = (const float4*)(g_hstate + (size_t)(b * NH + h) * DST * HD);
        float4* hdst = (float4*)Hs;
#pragma unroll
        for (int i = 0; i < 4; i++) {
            const int idx = tid + i * 256;
            const int dq = (idx & 15) * 4;
            const float4 na = *(const float4*)(g_negA + h * HD + dq);
            float4 v = hsrc[idx];
            v.x *= na.x; v.y *= na.y; v.z *= na.z; v.w *= na.w;
            hdst[idx] = v;
        }
    }
    {
        const int lr = tid >> 2;
        const int base = (tid & 3) * 4;
        const float* crow = g_xBCa + (size_t)(b * LL + l0 + lr) * CONVD + DINNER + DST;
#pragma unroll
        for (int it = 0; it < 4; it++) {
            const int sq = base + it * 16;
            float4 v = *(const float4*)(crow + sq);
            Cs[sq + 0][lr] = v.x; Cs[sq + 1][lr] = v.y;
            Cs[sq + 2][lr] = v.z; Cs[sq + 3][lr] = v.w;
        }
    }
    __syncthreads();

    float acc[4][4];
#pragma unroll
    for (int i = 0; i < 4; i++)
#pragma unroll
        for (int j = 0; j < 4; j++) acc[i][j] = 0.f;

#pragma unroll 16
    for (int s = 0; s < 64; s++) {
        float4 a = *(const float4*)&Cs[s][ty * 4];
        float4 hv = *(const float4*)&Hs[s][tx * 4];
        float av[4] = {a.x, a.y, a.z, a.w};
        float hvv[4] = {hv.x, hv.y, hv.z, hv.w};
#pragma unroll
        for (int i = 0; i < 4; i++)
#pragma unroll
            for (int j = 0; j < 4; j++)
                acc[i][j] = fmaf(av[i], hvv[j], acc[i][j]);
    }

    const float dcoef = Dp[h];
#pragma unroll
    for (int i = 0; i < 4; i++) {
        const int l = l0 + ty * 4 + i;
        const size_t r = (size_t)(b * LL + l);
        const int c = h * HD + tx * 4;
        const float4 xs = *(const float4*)(g_xBCa + r * CONVD + c);
        float4 o;
        o.x = acc[i][0] + xs.x * dcoef;
        o.y = acc[i][1] + xs.y * dcoef;
        o.z = acc[i][2] + xs.z * dcoef;
        o.w = acc[i][3] + xs.w * dcoef;
        *(float4*)(g_y + r * DINNER + c) = o;
    }
}

// ------- g = y*silu(z); LayerNorm -> g_gn (tf32-rounded, k-PERMUTED store), float4 loads -------
__global__ void __launch_bounds__(192) ln_kernel(
    const float* __restrict__ nw, const float* __restrict__ nb)
{
    const int bl = blockIdx.x;
    const int tid = threadIdx.x;
    const int c = tid * 4;
    __shared__ float smu[6], sv[6];

    const float4 y4 = *(const float4*)(g_y + (size_t)bl * DINNER + c);
    const float4 z4 = *(const float4*)(g_z + (size_t)bl * DINNER + c);
    float v[4];
    v[0] = y4.x * (z4.x / (1.f + expf(-z4.x)));
    v[1] = y4.y * (z4.y / (1.f + expf(-z4.y)));
    v[2] = y4.z * (z4.z / (1.f + expf(-z4.z)));
    v[3] = y4.w * (z4.w / (1.f + expf(-z4.w)));
    float s = v[0] + v[1] + v[2] + v[3];
    float s2 = v[0] * v[0] + v[1] * v[1] + v[2] * v[2] + v[3] * v[3];
#pragma unroll
    for (int o = 16; o > 0; o >>= 1) {
        s += __shfl_xor_sync(0xffffffffu, s, o);
        s2 += __shfl_xor_sync(0xffffffffu, s2, o);
    }
    const int w = tid >> 5;
    if ((tid & 31) == 0) { smu[w] = s; sv[w] = s2; }
    __syncthreads();
    float ts = 0.f, ts2 = 0.f;
#pragma unroll
    for (int i = 0; i < 6; i++) { ts += smu[i]; ts2 += sv[i]; }

    const float mu = ts * (1.f / (float)DINNER);
    const float var = ts2 * (1.f / (float)DINNER) - mu * mu;
    const float rstd = rsqrtf(var + 1e-5f);
    const float4 w4 = *(const float4*)(nw + c);
    const float4 b4 = *(const float4*)(nb + c);
    const float wv[4] = {w4.x, w4.y, w4.z, w4.w};
    const float bv[4] = {b4.x, b4.y, b4.z, b4.w};
#pragma unroll
    for (int i = 0; i < 4; i++) {
        const int cc = c + i;
        const float o = (v[i] - mu) * rstd * wv[i] + bv[i];
        const int pc = (cc & ~15) | ((cc & 3) << 2) | ((cc >> 2) & 3);
        g_gn[(size_t)bl * DINNER + pc] = __uint_as_float(f2tf32(o));
    }
}

// ---------------- launch ----------------
extern "C" void kernel_launch(void* const* d_in, const int* in_sizes, int n_in,
                              void* d_out, int out_size)
{
    const float* x    = (const float*)d_in[0];   // [BL, 384]
    const float* win  = (const float*)d_in[1];   // [1676, 384]
    const float* cw   = (const float*)d_in[2];   // [896, 1, 3, 3]
    const float* cb   = (const float*)d_in[3];   // [896]
    const float* dtb  = (const float*)d_in[4];   // [12]
    const float* alog = (const float*)d_in[5];   // [768]
    const float* Dp   = (const float*)d_in[6];   // [12]
    const float* nw   = (const float*)d_in[7];   // [768]
    const float* nb   = (const float*)d_in[8];   // [768]
    const float* wout = (const float*)d_in[9];   // [384, 768]
    float* out = (float*)d_out;                  // [BL, 384]

    cudaFuncSetAttribute(gemm_mma<DMODEL, 0>,
                         cudaFuncAttributeMaxDynamicSharedMemorySize, GEMM_DSMEM);
    cudaFuncSetAttribute(gemm_mma<DINNER, 1>,
                         cudaFuncAttributeMaxDynamicSharedMemorySize, GEMM_DSMEM);

    float* xcvt;    cudaGetSymbolAddress((void**)&xcvt, g_xcvt);
    float* wincvt;  cudaGetSymbolAddress((void**)&wincvt, g_wincvt);
    float* woutcvt; cudaGetSymbolAddress((void**)&woutcvt, g_woutcvt);

    // prep: round/permute in-proj inputs, zero h_state, negA + weight transpose
    cvt_perm_kernel<<<(BL * DMODEL / 16 + 255) / 256, 256>>>(x, xcvt, BL * DMODEL / 16);
    cvt_perm_kernel<<<(DPROJ * DMODEL / 16 + 255) / 256, 256>>>(win, wincvt, DPROJ * DMODEL / 16);
    zero_hstate<<<384, 256>>>();
    prep_kernel<<<(9 * CONVD + 255) / 256, 256>>>(alog, cw);
    // in-proj GEMM (128x128) + split epilogue
    gemm_mma<DMODEL, 0><<<dim3(14, 196), 256, GEMM_DSMEM>>>(nullptr, dtb, DPROJ);
    // depthwise conv + silu (2 outputs/thread)
    conv_kernel<<<BL / 2, 224>>>(cb);
    // round+permute out-proj weight (independent)
    cvt_perm_kernel<<<(DMODEL * DINNER / 16 + 255) / 256, 256>>>(wout, woutcvt, DMODEL * DINNER / 16);
    // transpose-pooled B
    bpool_kernel<<<BL / 8, 128>>>();
    // split-K batched state GEMM (2 heads/CTA)
    hstate_kernel<<<dim3(7, 6, 8), 256>>>();
    // Ch (negA folded into Hs) + D*x -> y
    ch_kernel<<<dim3(49, 12, 8), 256>>>(Dp);
    // gate + LayerNorm (float4 loads, permuted tf32 store)
    ln_kernel<<<BL, 192>>>(nw, nb);
    // out-proj GEMM (N = 384 = 3 x 128 tiles)
    gemm_mma<DINNER, 1><<<dim3(3, 196), 256, GEMM_DSMEM>>>(out, nullptr, DMODEL);
}